// round 14
// baseline (speedup 1.0000x reference)
#include <cuda_runtime.h>
#include <cuda_fp16.h>
#include <math.h>
#include <stdint.h>

#define BATCH   4
#define SEQLEN  4096
#define DMODEL  1024
#define DINNER  2048
#define DSTATE  16
#define NHEADS  8
#define HEADDIM 256
#define CONVDIM 2080
#define DPROJ   4136
#define ZXS     4224
#define QC      64
#define NCHUNK  (SEQLEN/QC)
#define NTOK    (BATCH*SEQLEN)

// ---------------- scratch ----------------------------------------------------
__device__ __half g_zx[(size_t)NTOK * ZXS];          // in-proj output, fp16
__device__ __half g_Win[(size_t)DMODEL * ZXS];
__device__ __half g_u16[(size_t)NTOK * DMODEL];
__device__ __half g_Wout16[(size_t)DINNER * DMODEL];
__device__ float  g_c[(size_t)NTOK * DSTATE];        // conv+silu'd C channels (for yoff)
__device__ float  g_cs[NTOK * NHEADS];
__device__ float  g_states[BATCH * NCHUNK * NHEADS * HEADDIM * DSTATE];
__device__ float  g_prev[BATCH * NCHUNK * NHEADS * HEADDIM * DSTATE];
__device__ float  g_y[(size_t)NTOK * DINNER];
__device__ __half g_yn[(size_t)NTOK * DINNER];

// ---------------- fp16 permuted-layout offsets (in half units) --------------
__device__ __forceinline__ size_t aoffh(int m, int k, int K16) {
    return ((size_t)((m >> 4) * K16 + (k >> 4)) << 8)
         + ((((m & 7) << 2) + ((k & 7) >> 1)) << 3)
         + (((m >> 3) & 1) << 1) + (((k >> 3) & 1) << 2) + (k & 1);
}
__device__ __forceinline__ size_t boffh(int n, int k, int K16) {
    return ((size_t)((n >> 4) * K16 + (k >> 4)) << 8)
         + ((((n & 7) << 2) + ((k & 7) >> 1)) << 3)
         + (((n >> 3) & 1) << 2) + (((k >> 3) & 1) << 1) + (k & 1);
}

__device__ __forceinline__ void cpa16(void* s, const void* gp) {
    unsigned saddr = (unsigned)__cvta_generic_to_shared(s);
    asm volatile("cp.async.cg.shared.global [%0], [%1], 16;" :: "r"(saddr), "l"(gp));
}
__device__ __forceinline__ void mma_f16(float c[4], unsigned a0, unsigned a1,
                                        unsigned a2, unsigned a3,
                                        unsigned b0, unsigned b1) {
    asm volatile(
        "mma.sync.aligned.m16n8k16.row.col.f32.f16.f16.f32 "
        "{%0,%1,%2,%3}, {%4,%5,%6,%7}, {%8,%9}, {%0,%1,%2,%3};"
        : "+f"(c[0]), "+f"(c[1]), "+f"(c[2]), "+f"(c[3])
        : "r"(a0), "r"(a1), "r"(a2), "r"(a3), "r"(b0), "r"(b1));
}

// ======================= fp16 tensor-core GEMM (permuted) ===================
#define GEMM_SMEM (2 * 16384 * 2)   // 64 KB

extern __shared__ __half h_smem[];

template <bool HALF_OUT>
__global__ void __launch_bounds__(256, 2)
mma_gemm(const __half* __restrict__ A, const __half* __restrict__ B,
         void* __restrict__ Cv, int K, int ldc) {
    int tid = threadIdx.x, warp = tid >> 5, lane = tid & 31;
    int g = lane >> 2, tg = lane & 3;
    int warp_m = warp >> 2;
    int warp_n = warp & 3;
    int m0 = blockIdx.y * 128, n0 = blockIdx.x * 128;
    int K16 = K >> 4;
    const __half* Abase = A + (size_t)(m0 >> 4) * K16 * 256;
    const __half* Bbase = B + (size_t)(n0 >> 4) * K16 * 256;

    float acc[4][4][4];
    #pragma unroll
    for (int mi = 0; mi < 4; mi++)
        #pragma unroll
        for (int ni = 0; ni < 4; ni++)
            #pragma unroll
            for (int r = 0; r < 4; r++) acc[mi][ni][r] = 0.f;

    const int KT = K >> 6;

    auto load_tile = [&](int kt, int s) {
        __half* sA = h_smem + s * 16384;
        __half* sB = sA + 8192;
        #pragma unroll
        for (int j = 0; j < 4; j++) {
            int u = tid + 256 * j;
            int grp = u >> 7;
            int within = u & 127;
            cpa16(sA + u * 8, Abase + (size_t)grp * (K16 * 256) + kt * 1024 + within * 8);
            cpa16(sB + u * 8, Bbase + (size_t)grp * (K16 * 256) + kt * 1024 + within * 8);
        }
        asm volatile("cp.async.commit_group;");
    };

    load_tile(0, 0);

    for (int kt = 0; kt < KT; kt++) {
        int s = kt & 1;
        if (kt + 1 < KT) {
            load_tile(kt + 1, s ^ 1);
            asm volatile("cp.async.wait_group 1;");
        } else {
            asm volatile("cp.async.wait_group 0;");
        }
        __syncthreads();

        const __half* wA = h_smem + s * 16384 + (warp_m * 4) * 1024;
        const __half* wB = h_smem + s * 16384 + 8192 + (warp_n * 2) * 1024;

        #pragma unroll
        for (int ks = 0; ks < 4; ks++) {
            uint4 afr[4]; uint4 bq[2];
            #pragma unroll
            for (int mi = 0; mi < 4; mi++)
                afr[mi] = *(const uint4*)(wA + mi * 1024 + ks * 256 + lane * 8);
            #pragma unroll
            for (int nb = 0; nb < 2; nb++)
                bq[nb] = *(const uint4*)(wB + nb * 1024 + ks * 256 + lane * 8);
            #pragma unroll
            for (int mi = 0; mi < 4; mi++) {
                mma_f16(acc[mi][0], afr[mi].x, afr[mi].y, afr[mi].z, afr[mi].w, bq[0].x, bq[0].y);
                mma_f16(acc[mi][1], afr[mi].x, afr[mi].y, afr[mi].z, afr[mi].w, bq[0].z, bq[0].w);
                mma_f16(acc[mi][2], afr[mi].x, afr[mi].y, afr[mi].z, afr[mi].w, bq[1].x, bq[1].y);
                mma_f16(acc[mi][3], afr[mi].x, afr[mi].y, afr[mi].z, afr[mi].w, bq[1].z, bq[1].w);
            }
        }
        __syncthreads();
    }

    #pragma unroll
    for (int mi = 0; mi < 4; mi++) {
        #pragma unroll
        for (int ni = 0; ni < 4; ni++) {
            int row = m0 + warp_m * 64 + mi * 16 + g;
            int col = n0 + warp_n * 32 + ni * 8 + tg * 2;
            if (HALF_OUT) {
                __half* C = (__half*)Cv;
                *(__half2*)&C[(size_t)row * ldc + col] =
                    __floats2half2_rn(acc[mi][ni][0], acc[mi][ni][1]);
                *(__half2*)&C[(size_t)(row + 8) * ldc + col] =
                    __floats2half2_rn(acc[mi][ni][2], acc[mi][ni][3]);
            } else {
                float* C = (float*)Cv;
                *(float2*)&C[(size_t)row * ldc + col] =
                    make_float2(acc[mi][ni][0], acc[mi][ni][1]);
                *(float2*)&C[(size_t)(row + 8) * ldc + col] =
                    make_float2(acc[mi][ni][2], acc[mi][ni][3]);
            }
        }
    }
}

// ---------------- prepasses --------------------------------------------------
__global__ void cvt_u_kernel(const float* __restrict__ u) {
    int i = blockIdx.x * 256 + threadIdx.x;
    if (i >= NTOK * DMODEL) return;
    int m = i >> 10, k = i & 1023;
    g_u16[aoffh(m, k, 64)] = __float2half_rn(u[i]);
}
__global__ void pad_win_kernel(const float* __restrict__ W_in) {
    int i = blockIdx.x * 256 + threadIdx.x;
    if (i >= DMODEL * ZXS) return;
    int k = i / ZXS, n = i - k * ZXS;
    float v = (n < DPROJ) ? W_in[(size_t)k * DPROJ + n] : 0.f;
    g_Win[boffh(n, k, 64)] = __float2half_rn(v);
}
__global__ void cvt_wout_kernel(const float* __restrict__ W_out) {
    int i = blockIdx.x * 256 + threadIdx.x;
    if (i >= DINNER * DMODEL) return;
    int k = i >> 10, n = i & 1023;
    g_Wout16[boffh(n, k, 128)] = __float2half_rn(W_out[i]);
}

// ---------------- per-chunk: conv+silu, dt, cumsum, M, Y_diag, states -------
// Dynamic smem: sMt [64][64] (16KB) + sx [64][256] (64KB) = 80KB.
#define CHUNK_SMEM ((QC * QC + QC * HEADDIM) * 4)

extern __shared__ float cf_smem[];

__global__ void __launch_bounds__(256)
chunk_kernel(const float* __restrict__ A_log, const float* __restrict__ Dp,
             const float* __restrict__ dt_bias,
             const float* __restrict__ conv_w, const float* __restrict__ conv_b) {
    int h = blockIdx.x, c = blockIdx.y, b = blockIdx.z;
    int t0 = b * SEQLEN + c * QC;
    int tid = threadIdx.x;

    float* sMt = cf_smem;            // sMt[s][q] = M[q][s]
    float* sx  = cf_smem + QC * QC;  // sx[q][p]

    __shared__ float sB[QC][DSTATE];
    __shared__ float sC[QC][DSTATE];
    __shared__ float sE[QC][DSTATE];
    __shared__ float sdt[QC], scs[QC];

    bool bstart = (c == 0);

    // ---- x conv+silu: thread = channel ----
    {
        int wch = h * HEADDIM + tid;           // conv channel
        size_t col = DINNER + wch;             // zx column
        float w0 = conv_w[wch * 4 + 0], w1 = conv_w[wch * 4 + 1];
        float w2 = conv_w[wch * 4 + 2], w3 = conv_w[wch * 4 + 3];
        float bb = conv_b[wch];
        float v0 = 0.f, v1 = 0.f, v2 = 0.f;
        if (!bstart) {
            v0 = __half2float(g_zx[(size_t)(t0 - 3) * ZXS + col]);
            v1 = __half2float(g_zx[(size_t)(t0 - 2) * ZXS + col]);
            v2 = __half2float(g_zx[(size_t)(t0 - 1) * ZXS + col]);
        }
        #pragma unroll 4
        for (int t = 0; t < QC; t++) {
            float v3 = __half2float(g_zx[(size_t)(t0 + t) * ZXS + col]);
            float a = bb + v0 * w0 + v1 * w1 + v2 * w2 + v3 * w3;
            sx[t * HEADDIM + tid] = a / (1.f + __expf(-a));
            v0 = v1; v1 = v2; v2 = v3;
        }
    }
    // ---- B/C conv+silu: threads 0..31 ----
    if (tid < 32) {
        int wch = DINNER + tid;
        size_t col = (size_t)DINNER + DINNER + tid;
        float w0 = conv_w[wch * 4 + 0], w1 = conv_w[wch * 4 + 1];
        float w2 = conv_w[wch * 4 + 2], w3 = conv_w[wch * 4 + 3];
        float bb = conv_b[wch];
        float v0 = 0.f, v1 = 0.f, v2 = 0.f;
        if (!bstart) {
            v0 = __half2float(g_zx[(size_t)(t0 - 3) * ZXS + col]);
            v1 = __half2float(g_zx[(size_t)(t0 - 2) * ZXS + col]);
            v2 = __half2float(g_zx[(size_t)(t0 - 1) * ZXS + col]);
        }
        for (int t = 0; t < QC; t++) {
            float v3 = __half2float(g_zx[(size_t)(t0 + t) * ZXS + col]);
            float a = bb + v0 * w0 + v1 * w1 + v2 * w2 + v3 * w3;
            float val = a / (1.f + __expf(-a));
            if (tid < 16) sB[t][tid] = val;
            else {
                sC[t][tid - 16] = val;
                if (h == 0) g_c[(size_t)(t0 + t) * DSTATE + tid - 16] = val;
            }
            v0 = v1; v1 = v2; v2 = v3;
        }
    }
    // ---- dt ----
    if (tid >= 64 && tid < 128) {
        int t = tid - 64;
        float v = __half2float(g_zx[(size_t)(t0 + t) * ZXS + DINNER + CONVDIM + h]) + dt_bias[h];
        sdt[t] = (v > 20.f) ? v : log1pf(expf(v));
    }
    __syncthreads();

    float A = -expf(A_log[h]);
    if (tid == 0) {
        float run = 0.f;
        for (int q = 0; q < QC; q++) { run += sdt[q] * A; scs[q] = run; }
    }
    __syncthreads();
    if (tid < QC) g_cs[(t0 + tid) * NHEADS + h] = scs[tid];

    float cl = scs[QC - 1];
    for (int i = tid; i < QC * DSTATE; i += 256) {
        int q = i >> 4, n = i & 15;
        sE[q][n] = sB[q][n] * __expf(cl - scs[q]) * sdt[q];
    }
    for (int i = tid; i < QC * QC; i += 256) {
        int q = i >> 6, s = i & 63;
        float v = 0.f;
        if (s <= q) {
            float d = 0.f;
            #pragma unroll
            for (int n = 0; n < DSTATE; n++) d += sC[q][n] * sB[s][n];
            v = __expf(scs[q] - scs[s]) * d * sdt[s];
        }
        sMt[s * QC + q] = v;
    }
    __syncthreads();

    // ---- Y_diag: 8x8 microtile per thread ----
    int q0 = (tid >> 5) * 8;
    int p0 = (tid & 31) * 4;
    int p1 = p0 + 128;

    float acc[8][8];
    #pragma unroll
    for (int i = 0; i < 8; i++)
        #pragma unroll
        for (int j = 0; j < 8; j++) acc[i][j] = 0.f;

    for (int s = 0; s < QC; s++) {
        float4 ma = *(const float4*)&sMt[s * QC + q0];
        float4 mb = *(const float4*)&sMt[s * QC + q0 + 4];
        float4 xa = *(const float4*)&sx[s * HEADDIM + p0];
        float4 xb = *(const float4*)&sx[s * HEADDIM + p1];
        float mv[8] = {ma.x, ma.y, ma.z, ma.w, mb.x, mb.y, mb.z, mb.w};
        float xv[8] = {xa.x, xa.y, xa.z, xa.w, xb.x, xb.y, xb.z, xb.w};
        #pragma unroll
        for (int i = 0; i < 8; i++)
            #pragma unroll
            for (int j = 0; j < 8; j++)
                acc[i][j] += mv[i] * xv[j];
    }

    float Dh = Dp[h];
    #pragma unroll
    for (int i = 0; i < 8; i++) {
        int q = q0 + i;
        size_t yb = (size_t)(t0 + q) * DINNER + h * HEADDIM;
        float4 o0, o1;
        o0.x = acc[i][0] + Dh * sx[q * HEADDIM + p0 + 0];
        o0.y = acc[i][1] + Dh * sx[q * HEADDIM + p0 + 1];
        o0.z = acc[i][2] + Dh * sx[q * HEADDIM + p0 + 2];
        o0.w = acc[i][3] + Dh * sx[q * HEADDIM + p0 + 3];
        o1.x = acc[i][4] + Dh * sx[q * HEADDIM + p1 + 0];
        o1.y = acc[i][5] + Dh * sx[q * HEADDIM + p1 + 1];
        o1.z = acc[i][6] + Dh * sx[q * HEADDIM + p1 + 2];
        o1.w = acc[i][7] + Dh * sx[q * HEADDIM + p1 + 3];
        *(float4*)&g_y[yb + p0] = o0;
        *(float4*)&g_y[yb + p1] = o1;
    }

    // ---- states: thread = one p, 16 n accumulators ----
    float accS[16];
    #pragma unroll
    for (int n = 0; n < 16; n++) accS[n] = 0.f;
    for (int q = 0; q < QC; q++) {
        float xs = sx[q * HEADDIM + tid];
        float4 e0 = *(const float4*)&sE[q][0];
        float4 e1 = *(const float4*)&sE[q][4];
        float4 e2 = *(const float4*)&sE[q][8];
        float4 e3 = *(const float4*)&sE[q][12];
        accS[0]  += e0.x * xs; accS[1]  += e0.y * xs; accS[2]  += e0.z * xs; accS[3]  += e0.w * xs;
        accS[4]  += e1.x * xs; accS[5]  += e1.y * xs; accS[6]  += e1.z * xs; accS[7]  += e1.w * xs;
        accS[8]  += e2.x * xs; accS[9]  += e2.y * xs; accS[10] += e2.z * xs; accS[11] += e2.w * xs;
        accS[12] += e3.x * xs; accS[13] += e3.y * xs; accS[14] += e3.z * xs; accS[15] += e3.w * xs;
    }
    size_t sb = ((size_t)((b * NCHUNK + c) * NHEADS + h)) * HEADDIM * DSTATE
                + (size_t)tid * DSTATE;
    #pragma unroll
    for (int n4 = 0; n4 < 4; n4++)
        *(float4*)&g_states[sb + n4 * 4] =
            make_float4(accS[n4 * 4], accS[n4 * 4 + 1], accS[n4 * 4 + 2], accS[n4 * 4 + 3]);
}

// ---------------- inter-chunk scan ------------------------------------------
__global__ void __launch_bounds__(512) scan_kernel() {
    int pb = blockIdx.x, h = blockIdx.y, b = blockIdx.z;
    int tid = threadIdx.x;
    int pl = tid >> 4, n = tid & 15;
    int p = pb * 32 + pl;
    float carry = 0.f;
    for (int c = 0; c < NCHUNK; c++) {
        size_t idx = ((size_t)((b * NCHUNK + c) * NHEADS + h)) * HEADDIM * DSTATE
                     + (size_t)p * DSTATE + n;
        g_prev[idx] = carry;
        float dec = __expf(g_cs[(b * SEQLEN + c * QC + QC - 1) * NHEADS + h]);
        carry = dec * carry + g_states[idx];
    }
}

// ---------------- Y_off ------------------------------------------------------
__global__ void __launch_bounds__(256) yoff_kernel() {
    int h = blockIdx.x, c = blockIdx.y, b = blockIdx.z;
    int t0 = b * SEQLEN + c * QC;
    int tid = threadIdx.x;

    __shared__ float sPrev[HEADDIM][DSTATE + 1];
    __shared__ float sC2[QC][DSTATE];
    __shared__ float sExp[QC];

    size_t pbase = ((size_t)((b * NCHUNK + c) * NHEADS + h)) * HEADDIM * DSTATE;
    for (int i = tid; i < HEADDIM * DSTATE; i += 256)
        sPrev[i >> 4][i & 15] = g_prev[pbase + i];
    for (int i = tid; i < QC * DSTATE; i += 256) {
        int q = i >> 4, n = i & 15;
        sC2[q][n] = g_c[(size_t)(t0 + q) * DSTATE + n];
    }
    if (tid < QC) sExp[tid] = __expf(g_cs[(t0 + tid) * NHEADS + h]);
    __syncthreads();

    for (int i = tid; i < QC * HEADDIM; i += 256) {
        int q = i >> 8, p = i & 255;
        float d = 0.f;
        #pragma unroll
        for (int n = 0; n < DSTATE; n++) d += sC2[q][n] * sPrev[p][n];
        size_t yi = (size_t)(t0 + q) * DINNER + h * HEADDIM + p;
        g_y[yi] += sExp[q] * d;
    }
}

// ---------------- gate + RMSNorm -> A-permuted fp16 -------------------------
__global__ void __launch_bounds__(256) gate_norm_kernel(const float* __restrict__ norm_w) {
    int t = blockIdx.x, tid = threadIdx.x;
    __shared__ float red[256];
    float v[8];
    float ss = 0.f;
    #pragma unroll
    for (int r = 0; r < 8; r++) {
        int i = r * 256 + tid;
        float y = g_y[(size_t)t * DINNER + i];
        float z = __half2float(g_zx[(size_t)t * ZXS + i]);
        float w = y * (z / (1.f + __expf(-z)));
        v[r] = w;
        ss += w * w;
    }
    red[tid] = ss;
    __syncthreads();
    for (int s = 128; s > 0; s >>= 1) {
        if (tid < s) red[tid] += red[tid + s];
        __syncthreads();
    }
    float scale = rsqrtf(red[0] / (float)DINNER + 1e-5f);
    #pragma unroll
    for (int r = 0; r < 8; r++) {
        int i = r * 256 + tid;
        g_yn[aoffh(t, i, 128)] = __float2half_rn(v[r] * scale * norm_w[i]);
    }
}

// ---------------- launch ----------------------------------------------------
extern "C" void kernel_launch(void* const* d_in, const int* in_sizes, int n_in,
                              void* d_out, int out_size) {
    const float* u       = (const float*)d_in[0];
    const float* W_in    = (const float*)d_in[1];
    const float* conv_w  = (const float*)d_in[2];
    const float* conv_b  = (const float*)d_in[3];
    const float* dt_bias = (const float*)d_in[4];
    const float* A_log   = (const float*)d_in[5];
    const float* Dv      = (const float*)d_in[6];
    const float* norm_w  = (const float*)d_in[7];
    const float* W_out   = (const float*)d_in[8];
    float* out = (float*)d_out;

    void* p;
    cudaGetSymbolAddress(&p, g_zx);     __half* zx   = (__half*)p;
    cudaGetSymbolAddress(&p, g_Win);    __half* win  = (__half*)p;
    cudaGetSymbolAddress(&p, g_u16);    __half* u16  = (__half*)p;
    cudaGetSymbolAddress(&p, g_Wout16); __half* wo16 = (__half*)p;
    cudaGetSymbolAddress(&p, g_yn);     __half* yn   = (__half*)p;

    cudaFuncSetAttribute(mma_gemm<true>,  cudaFuncAttributeMaxDynamicSharedMemorySize, GEMM_SMEM);
    cudaFuncSetAttribute(mma_gemm<false>, cudaFuncAttributeMaxDynamicSharedMemorySize, GEMM_SMEM);
    cudaFuncSetAttribute(chunk_kernel, cudaFuncAttributeMaxDynamicSharedMemorySize, CHUNK_SMEM);

    // prepasses
    pad_win_kernel<<<(DMODEL * ZXS + 255) / 256, 256>>>(W_in);
    cvt_u_kernel<<<(NTOK * DMODEL + 255) / 256, 256>>>(u);
    cvt_wout_kernel<<<(DINNER * DMODEL + 255) / 256, 256>>>(W_out);

    // 1) in-projection (fp16 output)
    mma_gemm<true><<<dim3(ZXS / 128, NTOK / 128), 256, GEMM_SMEM>>>(u16, win, zx, DMODEL, ZXS);

    // 2) per-chunk (conv+silu fused in)
    chunk_kernel<<<dim3(NHEADS, NCHUNK, BATCH), 256, CHUNK_SMEM>>>(
        A_log, Dv, dt_bias, conv_w, conv_b);

    // 3) inter-chunk scan
    scan_kernel<<<dim3(HEADDIM / 32, NHEADS, BATCH), 512>>>();

    // 4) Y_off
    yoff_kernel<<<dim3(NHEADS, NCHUNK, BATCH), 256>>>();

    // 5) gating + RMSNorm
    gate_norm_kernel<<<NTOK, 256>>>(norm_w);

    // 6) out-projection (fp32 output)
    mma_gemm<false><<<dim3(DMODEL / 128, NTOK / 128), 256, GEMM_SMEM>>>(yn, wo16, out, DINNER, DMODEL);
}

// round 15
// speedup vs baseline: 1.1325x; 1.1325x over previous
#include <cuda_runtime.h>
#include <cuda_fp16.h>
#include <math.h>
#include <stdint.h>

#define BATCH   4
#define SEQLEN  4096
#define DMODEL  1024
#define DINNER  2048
#define DSTATE  16
#define NHEADS  8
#define HEADDIM 256
#define CONVDIM 2080
#define DPROJ   4136
#define ZXS     4224
#define QC      64
#define NCHUNK  (SEQLEN/QC)
#define NTOK    (BATCH*SEQLEN)

// ---------------- scratch ----------------------------------------------------
__device__ __half g_zx[(size_t)NTOK * ZXS];          // in-proj output, fp16
__device__ __half g_Win[(size_t)DMODEL * ZXS];
__device__ __half g_u16[(size_t)NTOK * DMODEL];
__device__ __half g_Wout16[(size_t)DINNER * DMODEL];
__device__ float  g_xbc[(size_t)NTOK * CONVDIM];
__device__ float  g_cs[NTOK * NHEADS];
__device__ float  g_states[BATCH * NCHUNK * NHEADS * HEADDIM * DSTATE];
__device__ float  g_prev[BATCH * NCHUNK * NHEADS * HEADDIM * DSTATE];
__device__ float  g_y[(size_t)NTOK * DINNER];
__device__ __half g_yn[(size_t)NTOK * DINNER];

// ---------------- fp16 permuted-layout offsets (in half units) --------------
__device__ __forceinline__ size_t aoffh(int m, int k, int K16) {
    return ((size_t)((m >> 4) * K16 + (k >> 4)) << 8)
         + ((((m & 7) << 2) + ((k & 7) >> 1)) << 3)
         + (((m >> 3) & 1) << 1) + (((k >> 3) & 1) << 2) + (k & 1);
}
__device__ __forceinline__ size_t boffh(int n, int k, int K16) {
    return ((size_t)((n >> 4) * K16 + (k >> 4)) << 8)
         + ((((n & 7) << 2) + ((k & 7) >> 1)) << 3)
         + (((n >> 3) & 1) << 2) + (((k >> 3) & 1) << 1) + (k & 1);
}

__device__ __forceinline__ void cpa16(void* s, const void* gp) {
    unsigned saddr = (unsigned)__cvta_generic_to_shared(s);
    asm volatile("cp.async.cg.shared.global [%0], [%1], 16;" :: "r"(saddr), "l"(gp));
}
__device__ __forceinline__ void mma_f16(float c[4], unsigned a0, unsigned a1,
                                        unsigned a2, unsigned a3,
                                        unsigned b0, unsigned b1) {
    asm volatile(
        "mma.sync.aligned.m16n8k16.row.col.f32.f16.f16.f32 "
        "{%0,%1,%2,%3}, {%4,%5,%6,%7}, {%8,%9}, {%0,%1,%2,%3};"
        : "+f"(c[0]), "+f"(c[1]), "+f"(c[2]), "+f"(c[3])
        : "r"(a0), "r"(a1), "r"(a2), "r"(a3), "r"(b0), "r"(b1));
}

// ======================= fp16 tensor-core GEMM (permuted) ===================
#define GEMM_SMEM (2 * 16384 * 2)   // 64 KB

extern __shared__ __half h_smem[];

template <bool HALF_OUT>
__global__ void __launch_bounds__(256, 2)
mma_gemm(const __half* __restrict__ A, const __half* __restrict__ B,
         void* __restrict__ Cv, int K, int ldc) {
    int tid = threadIdx.x, warp = tid >> 5, lane = tid & 31;
    int g = lane >> 2, tg = lane & 3;
    int warp_m = warp >> 2;
    int warp_n = warp & 3;
    int m0 = blockIdx.y * 128, n0 = blockIdx.x * 128;
    int K16 = K >> 4;
    const __half* Abase = A + (size_t)(m0 >> 4) * K16 * 256;
    const __half* Bbase = B + (size_t)(n0 >> 4) * K16 * 256;

    float acc[4][4][4];
    #pragma unroll
    for (int mi = 0; mi < 4; mi++)
        #pragma unroll
        for (int ni = 0; ni < 4; ni++)
            #pragma unroll
            for (int r = 0; r < 4; r++) acc[mi][ni][r] = 0.f;

    const int KT = K >> 6;

    auto load_tile = [&](int kt, int s) {
        __half* sA = h_smem + s * 16384;
        __half* sB = sA + 8192;
        #pragma unroll
        for (int j = 0; j < 4; j++) {
            int u = tid + 256 * j;
            int grp = u >> 7;
            int within = u & 127;
            cpa16(sA + u * 8, Abase + (size_t)grp * (K16 * 256) + kt * 1024 + within * 8);
            cpa16(sB + u * 8, Bbase + (size_t)grp * (K16 * 256) + kt * 1024 + within * 8);
        }
        asm volatile("cp.async.commit_group;");
    };

    load_tile(0, 0);

    for (int kt = 0; kt < KT; kt++) {
        int s = kt & 1;
        if (kt + 1 < KT) {
            load_tile(kt + 1, s ^ 1);
            asm volatile("cp.async.wait_group 1;");
        } else {
            asm volatile("cp.async.wait_group 0;");
        }
        __syncthreads();

        const __half* wA = h_smem + s * 16384 + (warp_m * 4) * 1024;
        const __half* wB = h_smem + s * 16384 + 8192 + (warp_n * 2) * 1024;

        #pragma unroll
        for (int ks = 0; ks < 4; ks++) {
            uint4 afr[4]; uint4 bq[2];
            #pragma unroll
            for (int mi = 0; mi < 4; mi++)
                afr[mi] = *(const uint4*)(wA + mi * 1024 + ks * 256 + lane * 8);
            #pragma unroll
            for (int nb = 0; nb < 2; nb++)
                bq[nb] = *(const uint4*)(wB + nb * 1024 + ks * 256 + lane * 8);
            #pragma unroll
            for (int mi = 0; mi < 4; mi++) {
                mma_f16(acc[mi][0], afr[mi].x, afr[mi].y, afr[mi].z, afr[mi].w, bq[0].x, bq[0].y);
                mma_f16(acc[mi][1], afr[mi].x, afr[mi].y, afr[mi].z, afr[mi].w, bq[0].z, bq[0].w);
                mma_f16(acc[mi][2], afr[mi].x, afr[mi].y, afr[mi].z, afr[mi].w, bq[1].x, bq[1].y);
                mma_f16(acc[mi][3], afr[mi].x, afr[mi].y, afr[mi].z, afr[mi].w, bq[1].z, bq[1].w);
            }
        }
        __syncthreads();
    }

    #pragma unroll
    for (int mi = 0; mi < 4; mi++) {
        #pragma unroll
        for (int ni = 0; ni < 4; ni++) {
            int row = m0 + warp_m * 64 + mi * 16 + g;
            int col = n0 + warp_n * 32 + ni * 8 + tg * 2;
            if (HALF_OUT) {
                __half* C = (__half*)Cv;
                *(__half2*)&C[(size_t)row * ldc + col] =
                    __floats2half2_rn(acc[mi][ni][0], acc[mi][ni][1]);
                *(__half2*)&C[(size_t)(row + 8) * ldc + col] =
                    __floats2half2_rn(acc[mi][ni][2], acc[mi][ni][3]);
            } else {
                float* C = (float*)Cv;
                *(float2*)&C[(size_t)row * ldc + col] =
                    make_float2(acc[mi][ni][0], acc[mi][ni][1]);
                *(float2*)&C[(size_t)(row + 8) * ldc + col] =
                    make_float2(acc[mi][ni][2], acc[mi][ni][3]);
            }
        }
    }
}

// ---------------- prepasses --------------------------------------------------
__global__ void cvt_u_kernel(const float* __restrict__ u) {
    int i = blockIdx.x * 256 + threadIdx.x;
    if (i >= NTOK * DMODEL) return;
    int m = i >> 10, k = i & 1023;
    g_u16[aoffh(m, k, 64)] = __float2half_rn(u[i]);
}
__global__ void pad_win_kernel(const float* __restrict__ W_in) {
    int i = blockIdx.x * 256 + threadIdx.x;
    if (i >= DMODEL * ZXS) return;
    int k = i / ZXS, n = i - k * ZXS;
    float v = (n < DPROJ) ? W_in[(size_t)k * DPROJ + n] : 0.f;
    g_Win[boffh(n, k, 64)] = __float2half_rn(v);
}
__global__ void cvt_wout_kernel(const float* __restrict__ W_out) {
    int i = blockIdx.x * 256 + threadIdx.x;
    if (i >= DINNER * DMODEL) return;
    int k = i >> 10, n = i & 1023;
    g_Wout16[boffh(n, k, 128)] = __float2half_rn(W_out[i]);
}

// ---------------- tiled depthwise causal conv + silu (half2 loads) ----------
#define CT_T 64
#define CT_C 128
__global__ void __launch_bounds__(256)
conv_silu_kernel(const float* __restrict__ conv_w, const float* __restrict__ conv_b) {
    __shared__ float sx[CT_T + 3][CT_C];
    int c0 = blockIdx.x * CT_C;
    int t0 = blockIdx.y * CT_T;
    int tid = threadIdx.x;
    bool bstart = ((t0 & (SEQLEN - 1)) == 0);

    // (CT_T+3) rows x 64 half2 pairs
    for (int i = tid; i < (CT_T + 3) * (CT_C / 2); i += 256) {
        int r = i >> 6, j = i & 63;
        int c = c0 + j * 2;
        float2 v = make_float2(0.f, 0.f);
        if (c < CONVDIM && !(bstart && r < 3)) {
            __half2 hv = *(const __half2*)&g_zx[(size_t)(t0 - 3 + r) * ZXS + DINNER + c];
            v = __half22float2(hv);
        }
        sx[r][j * 2]     = v.x;
        sx[r][j * 2 + 1] = v.y;
    }
    __syncthreads();

    int cl = tid & (CT_C - 1);
    int tbase = (tid >> 7) * (CT_T / 2);
    int c = c0 + cl;
    if (c >= CONVDIM) return;
    float w0 = conv_w[c * 4 + 0], w1 = conv_w[c * 4 + 1];
    float w2 = conv_w[c * 4 + 2], w3 = conv_w[c * 4 + 3];
    float bb = conv_b[c];
    #pragma unroll 8
    for (int i = 0; i < CT_T / 2; i++) {
        int tl = tbase + i;
        float a = bb + sx[tl][cl] * w0 + sx[tl + 1][cl] * w1
                     + sx[tl + 2][cl] * w2 + sx[tl + 3][cl] * w3;
        g_xbc[(size_t)(t0 + tl) * CONVDIM + c] = a / (1.f + __expf(-a));
    }
}

// ---------------- per-chunk: dt, cumsum, M, Y_diag(+D*x), states ------------
#define CHUNK_SMEM ((QC * QC + QC * HEADDIM) * 4)

extern __shared__ float cf_smem[];

__global__ void __launch_bounds__(256)
chunk_kernel(const float* __restrict__ A_log, const float* __restrict__ Dp,
             const float* __restrict__ dt_bias) {
    int h = blockIdx.x, c = blockIdx.y, b = blockIdx.z;
    int t0 = b * SEQLEN + c * QC;
    int tid = threadIdx.x;

    float* sMt = cf_smem;            // sMt[s][q] = M[q][s]
    float* sx  = cf_smem + QC * QC;  // sx[q][p]

    __shared__ float sB[QC][DSTATE];
    __shared__ float sC[QC][DSTATE];
    __shared__ float sE[QC][DSTATE];
    __shared__ float sdt[QC], scs[QC];

    for (int i = tid; i < QC * DSTATE; i += 256) {
        int q = i >> 4, n = i & 15;
        size_t base = (size_t)(t0 + q) * CONVDIM + DINNER;
        sB[q][n] = g_xbc[base + n];
        sC[q][n] = g_xbc[base + DSTATE + n];
    }
    if (tid < QC) {
        float v = __half2float(g_zx[(size_t)(t0 + tid) * ZXS + DINNER + CONVDIM + h]) + dt_bias[h];
        sdt[tid] = (v > 20.f) ? v : log1pf(expf(v));
    }
    #pragma unroll
    for (int j = 0; j < 16; j++) {
        int u = tid + 256 * j;
        int q = u >> 6, p4 = (u & 63) * 4;
        *(float4*)&sx[q * HEADDIM + p4] =
            *(const float4*)&g_xbc[(size_t)(t0 + q) * CONVDIM + h * HEADDIM + p4];
    }
    __syncthreads();

    float A = -expf(A_log[h]);
    if (tid == 0) {
        float run = 0.f;
        for (int q = 0; q < QC; q++) { run += sdt[q] * A; scs[q] = run; }
    }
    __syncthreads();
    if (tid < QC) g_cs[(t0 + tid) * NHEADS + h] = scs[tid];

    float cl = scs[QC - 1];
    for (int i = tid; i < QC * DSTATE; i += 256) {
        int q = i >> 4, n = i & 15;
        sE[q][n] = sB[q][n] * __expf(cl - scs[q]) * sdt[q];
    }
    for (int i = tid; i < QC * QC; i += 256) {
        int q = i >> 6, s = i & 63;
        float v = 0.f;
        if (s <= q) {
            float d = 0.f;
            #pragma unroll
            for (int n = 0; n < DSTATE; n++) d += sC[q][n] * sB[s][n];
            v = __expf(scs[q] - scs[s]) * d * sdt[s];
        }
        sMt[s * QC + q] = v;
    }
    __syncthreads();

    // ---- Y_diag: 8x8 microtile per thread ----
    int q0 = (tid >> 5) * 8;
    int p0 = (tid & 31) * 4;
    int p1 = p0 + 128;

    float acc[8][8];
    #pragma unroll
    for (int i = 0; i < 8; i++)
        #pragma unroll
        for (int j = 0; j < 8; j++) acc[i][j] = 0.f;

    for (int s = 0; s < QC; s++) {
        float4 ma = *(const float4*)&sMt[s * QC + q0];
        float4 mb = *(const float4*)&sMt[s * QC + q0 + 4];
        float4 xa = *(const float4*)&sx[s * HEADDIM + p0];
        float4 xb = *(const float4*)&sx[s * HEADDIM + p1];
        float mv[8] = {ma.x, ma.y, ma.z, ma.w, mb.x, mb.y, mb.z, mb.w};
        float xv[8] = {xa.x, xa.y, xa.z, xa.w, xb.x, xb.y, xb.z, xb.w};
        #pragma unroll
        for (int i = 0; i < 8; i++)
            #pragma unroll
            for (int j = 0; j < 8; j++)
                acc[i][j] += mv[i] * xv[j];
    }

    float Dh = Dp[h];
    #pragma unroll
    for (int i = 0; i < 8; i++) {
        int q = q0 + i;
        size_t yb = (size_t)(t0 + q) * DINNER + h * HEADDIM;
        float4 o0, o1;
        o0.x = acc[i][0] + Dh * sx[q * HEADDIM + p0 + 0];
        o0.y = acc[i][1] + Dh * sx[q * HEADDIM + p0 + 1];
        o0.z = acc[i][2] + Dh * sx[q * HEADDIM + p0 + 2];
        o0.w = acc[i][3] + Dh * sx[q * HEADDIM + p0 + 3];
        o1.x = acc[i][4] + Dh * sx[q * HEADDIM + p1 + 0];
        o1.y = acc[i][5] + Dh * sx[q * HEADDIM + p1 + 1];
        o1.z = acc[i][6] + Dh * sx[q * HEADDIM + p1 + 2];
        o1.w = acc[i][7] + Dh * sx[q * HEADDIM + p1 + 3];
        *(float4*)&g_y[yb + p0] = o0;
        *(float4*)&g_y[yb + p1] = o1;
    }

    // ---- states: thread = one p, 16 n accumulators ----
    float accS[16];
    #pragma unroll
    for (int n = 0; n < 16; n++) accS[n] = 0.f;
    for (int q = 0; q < QC; q++) {
        float xs = sx[q * HEADDIM + tid];
        float4 e0 = *(const float4*)&sE[q][0];
        float4 e1 = *(const float4*)&sE[q][4];
        float4 e2 = *(const float4*)&sE[q][8];
        float4 e3 = *(const float4*)&sE[q][12];
        accS[0]  += e0.x * xs; accS[1]  += e0.y * xs; accS[2]  += e0.z * xs; accS[3]  += e0.w * xs;
        accS[4]  += e1.x * xs; accS[5]  += e1.y * xs; accS[6]  += e1.z * xs; accS[7]  += e1.w * xs;
        accS[8]  += e2.x * xs; accS[9]  += e2.y * xs; accS[10] += e2.z * xs; accS[11] += e2.w * xs;
        accS[12] += e3.x * xs; accS[13] += e3.y * xs; accS[14] += e3.z * xs; accS[15] += e3.w * xs;
    }
    size_t sb = ((size_t)((b * NCHUNK + c) * NHEADS + h)) * HEADDIM * DSTATE
                + (size_t)tid * DSTATE;
    #pragma unroll
    for (int n4 = 0; n4 < 4; n4++)
        *(float4*)&g_states[sb + n4 * 4] =
            make_float4(accS[n4 * 4], accS[n4 * 4 + 1], accS[n4 * 4 + 2], accS[n4 * 4 + 3]);
}

// ---------------- inter-chunk scan ------------------------------------------
__global__ void __launch_bounds__(512) scan_kernel() {
    int pb = blockIdx.x, h = blockIdx.y, b = blockIdx.z;
    int tid = threadIdx.x;
    int pl = tid >> 4, n = tid & 15;
    int p = pb * 32 + pl;
    float carry = 0.f;
    for (int c = 0; c < NCHUNK; c++) {
        size_t idx = ((size_t)((b * NCHUNK + c) * NHEADS + h)) * HEADDIM * DSTATE
                     + (size_t)p * DSTATE + n;
        g_prev[idx] = carry;
        float dec = __expf(g_cs[(b * SEQLEN + c * QC + QC - 1) * NHEADS + h]);
        carry = dec * carry + g_states[idx];
    }
}

// ---------------- Y_off ------------------------------------------------------
__global__ void __launch_bounds__(256) yoff_kernel() {
    int h = blockIdx.x, c = blockIdx.y, b = blockIdx.z;
    int t0 = b * SEQLEN + c * QC;
    int tid = threadIdx.x;

    __shared__ float sPrev[HEADDIM][DSTATE + 1];
    __shared__ float sC2[QC][DSTATE];
    __shared__ float sExp[QC];

    size_t pbase = ((size_t)((b * NCHUNK + c) * NHEADS + h)) * HEADDIM * DSTATE;
    for (int i = tid; i < HEADDIM * DSTATE; i += 256)
        sPrev[i >> 4][i & 15] = g_prev[pbase + i];
    for (int i = tid; i < QC * DSTATE; i += 256) {
        int q = i >> 4, n = i & 15;
        sC2[q][n] = g_xbc[(size_t)(t0 + q) * CONVDIM + DINNER + DSTATE + n];
    }
    if (tid < QC) sExp[tid] = __expf(g_cs[(t0 + tid) * NHEADS + h]);
    __syncthreads();

    for (int i = tid; i < QC * HEADDIM; i += 256) {
        int q = i >> 8, p = i & 255;
        float d = 0.f;
        #pragma unroll
        for (int n = 0; n < DSTATE; n++) d += sC2[q][n] * sPrev[p][n];
        size_t yi = (size_t)(t0 + q) * DINNER + h * HEADDIM + p;
        g_y[yi] += sExp[q] * d;
    }
}

// ---------------- gate + RMSNorm (consecutive-8 per thread) ------------------
__global__ void __launch_bounds__(256) gate_norm_kernel(const float* __restrict__ norm_w) {
    int t = blockIdx.x, tid = threadIdx.x;
    __shared__ float red[256];
    int base = tid * 8;

    float y[8], z[8];
    *(float4*)&y[0] = *(const float4*)&g_y[(size_t)t * DINNER + base];
    *(float4*)&y[4] = *(const float4*)&g_y[(size_t)t * DINNER + base + 4];
    {
        uint4 hz = *(const uint4*)&g_zx[(size_t)t * ZXS + base];
        const __half2* hp = (const __half2*)&hz;
        #pragma unroll
        for (int j = 0; j < 4; j++) {
            float2 f = __half22float2(hp[j]);
            z[j * 2] = f.x;
            z[j * 2 + 1] = f.y;
        }
    }
    float v[8];
    float ss = 0.f;
    #pragma unroll
    for (int r = 0; r < 8; r++) {
        float w = y[r] * (z[r] / (1.f + __expf(-z[r])));
        v[r] = w;
        ss += w * w;
    }
    red[tid] = ss;
    __syncthreads();
    for (int s = 128; s > 0; s >>= 1) {
        if (tid < s) red[tid] += red[tid + s];
        __syncthreads();
    }
    float scale = rsqrtf(red[0] / (float)DINNER + 1e-5f);
    #pragma unroll
    for (int r = 0; r < 8; r++) {
        int i = base + r;
        g_yn[aoffh(t, i, 128)] = __float2half_rn(v[r] * scale * norm_w[i]);
    }
}

// ---------------- launch ----------------------------------------------------
extern "C" void kernel_launch(void* const* d_in, const int* in_sizes, int n_in,
                              void* d_out, int out_size) {
    const float* u       = (const float*)d_in[0];
    const float* W_in    = (const float*)d_in[1];
    const float* conv_w  = (const float*)d_in[2];
    const float* conv_b  = (const float*)d_in[3];
    const float* dt_bias = (const float*)d_in[4];
    const float* A_log   = (const float*)d_in[5];
    const float* Dv      = (const float*)d_in[6];
    const float* norm_w  = (const float*)d_in[7];
    const float* W_out   = (const float*)d_in[8];
    float* out = (float*)d_out;

    void* p;
    cudaGetSymbolAddress(&p, g_zx);     __half* zx   = (__half*)p;
    cudaGetSymbolAddress(&p, g_Win);    __half* win  = (__half*)p;
    cudaGetSymbolAddress(&p, g_u16);    __half* u16  = (__half*)p;
    cudaGetSymbolAddress(&p, g_Wout16); __half* wo16 = (__half*)p;
    cudaGetSymbolAddress(&p, g_yn);     __half* yn   = (__half*)p;

    cudaFuncSetAttribute(mma_gemm<true>,  cudaFuncAttributeMaxDynamicSharedMemorySize, GEMM_SMEM);
    cudaFuncSetAttribute(mma_gemm<false>, cudaFuncAttributeMaxDynamicSharedMemorySize, GEMM_SMEM);
    cudaFuncSetAttribute(chunk_kernel, cudaFuncAttributeMaxDynamicSharedMemorySize, CHUNK_SMEM);

    // prepasses
    pad_win_kernel<<<(DMODEL * ZXS + 255) / 256, 256>>>(W_in);
    cvt_u_kernel<<<(NTOK * DMODEL + 255) / 256, 256>>>(u);
    cvt_wout_kernel<<<(DINNER * DMODEL + 255) / 256, 256>>>(W_out);

    // 1) in-projection (fp16 output)
    mma_gemm<true><<<dim3(ZXS / 128, NTOK / 128), 256, GEMM_SMEM>>>(u16, win, zx, DMODEL, ZXS);

    // 2) conv + silu
    conv_silu_kernel<<<dim3((CONVDIM + CT_C - 1) / CT_C, NTOK / CT_T), 256>>>(conv_w, conv_b);

    // 3) per-chunk
    chunk_kernel<<<dim3(NHEADS, NCHUNK, BATCH), 256, CHUNK_SMEM>>>(A_log, Dv, dt_bias);

    // 4) inter-chunk scan
    scan_kernel<<<dim3(HEADDIM / 32, NHEADS, BATCH), 512>>>();

    // 5) Y_off
    yoff_kernel<<<dim3(NHEADS, NCHUNK, BATCH), 256>>>();

    // 6) gating + RMSNorm
    gate_norm_kernel<<<NTOK, 256>>>(norm_w);

    // 7) out-projection (fp32 output)
    mma_gemm<false><<<dim3(DMODEL / 128, NTOK / 128), 256, GEMM_SMEM>>>(yn, wo16, out, DINNER, DMODEL);
}

// round 16
// speedup vs baseline: 1.2911x; 1.1401x over previous
#include <cuda_runtime.h>
#include <cuda_fp16.h>
#include <math.h>
#include <stdint.h>

#define BATCH   4
#define SEQLEN  4096
#define DMODEL  1024
#define DINNER  2048
#define DSTATE  16
#define NHEADS  8
#define HEADDIM 256
#define CONVDIM 2080
#define DPROJ   4136
#define ZXS     4224
#define QC      64
#define NCHUNK  (SEQLEN/QC)
#define NTOK    (BATCH*SEQLEN)

// ---------------- scratch ----------------------------------------------------
__device__ __half g_zx[(size_t)NTOK * ZXS];          // in-proj output, fp16
__device__ __half g_Win[(size_t)DMODEL * ZXS];
__device__ __half g_u16[(size_t)NTOK * DMODEL];
__device__ __half g_Wout16[(size_t)DINNER * DMODEL];
__device__ float  g_xbc[(size_t)NTOK * CONVDIM];
__device__ float  g_cs[NTOK * NHEADS];
__device__ float  g_states[BATCH * NCHUNK * NHEADS * HEADDIM * DSTATE];
__device__ float  g_prev[BATCH * NCHUNK * NHEADS * HEADDIM * DSTATE];
__device__ __half g_y16[(size_t)NTOK * DINNER];      // y (diag + off), fp16
__device__ __half g_yn[(size_t)NTOK * DINNER];

// ---------------- fp16 permuted-layout offsets (in half units) --------------
__device__ __forceinline__ size_t aoffh(int m, int k, int K16) {
    return ((size_t)((m >> 4) * K16 + (k >> 4)) << 8)
         + ((((m & 7) << 2) + ((k & 7) >> 1)) << 3)
         + (((m >> 3) & 1) << 1) + (((k >> 3) & 1) << 2) + (k & 1);
}
__device__ __forceinline__ size_t boffh(int n, int k, int K16) {
    return ((size_t)((n >> 4) * K16 + (k >> 4)) << 8)
         + ((((n & 7) << 2) + ((k & 7) >> 1)) << 3)
         + (((n >> 3) & 1) << 2) + (((k >> 3) & 1) << 1) + (k & 1);
}

__device__ __forceinline__ void cpa16(void* s, const void* gp) {
    unsigned saddr = (unsigned)__cvta_generic_to_shared(s);
    asm volatile("cp.async.cg.shared.global [%0], [%1], 16;" :: "r"(saddr), "l"(gp));
}
__device__ __forceinline__ void mma_f16(float c[4], unsigned a0, unsigned a1,
                                        unsigned a2, unsigned a3,
                                        unsigned b0, unsigned b1) {
    asm volatile(
        "mma.sync.aligned.m16n8k16.row.col.f32.f16.f16.f32 "
        "{%0,%1,%2,%3}, {%4,%5,%6,%7}, {%8,%9}, {%0,%1,%2,%3};"
        : "+f"(c[0]), "+f"(c[1]), "+f"(c[2]), "+f"(c[3])
        : "r"(a0), "r"(a1), "r"(a2), "r"(a3), "r"(b0), "r"(b1));
}

// ======================= fp16 tensor-core GEMM (permuted) ===================
#define GEMM_SMEM (2 * 16384 * 2)   // 64 KB

extern __shared__ __half h_smem[];

template <bool HALF_OUT>
__global__ void __launch_bounds__(256, 2)
mma_gemm(const __half* __restrict__ A, const __half* __restrict__ B,
         void* __restrict__ Cv, int K, int ldc) {
    int tid = threadIdx.x, warp = tid >> 5, lane = tid & 31;
    int g = lane >> 2, tg = lane & 3;
    int warp_m = warp >> 2;
    int warp_n = warp & 3;
    int m0 = blockIdx.y * 128, n0 = blockIdx.x * 128;
    int K16 = K >> 4;
    const __half* Abase = A + (size_t)(m0 >> 4) * K16 * 256;
    const __half* Bbase = B + (size_t)(n0 >> 4) * K16 * 256;

    float acc[4][4][4];
    #pragma unroll
    for (int mi = 0; mi < 4; mi++)
        #pragma unroll
        for (int ni = 0; ni < 4; ni++)
            #pragma unroll
            for (int r = 0; r < 4; r++) acc[mi][ni][r] = 0.f;

    const int KT = K >> 6;

    auto load_tile = [&](int kt, int s) {
        __half* sA = h_smem + s * 16384;
        __half* sB = sA + 8192;
        #pragma unroll
        for (int j = 0; j < 4; j++) {
            int u = tid + 256 * j;
            int grp = u >> 7;
            int within = u & 127;
            cpa16(sA + u * 8, Abase + (size_t)grp * (K16 * 256) + kt * 1024 + within * 8);
            cpa16(sB + u * 8, Bbase + (size_t)grp * (K16 * 256) + kt * 1024 + within * 8);
        }
        asm volatile("cp.async.commit_group;");
    };

    load_tile(0, 0);

    for (int kt = 0; kt < KT; kt++) {
        int s = kt & 1;
        if (kt + 1 < KT) {
            load_tile(kt + 1, s ^ 1);
            asm volatile("cp.async.wait_group 1;");
        } else {
            asm volatile("cp.async.wait_group 0;");
        }
        __syncthreads();

        const __half* wA = h_smem + s * 16384 + (warp_m * 4) * 1024;
        const __half* wB = h_smem + s * 16384 + 8192 + (warp_n * 2) * 1024;

        #pragma unroll
        for (int ks = 0; ks < 4; ks++) {
            uint4 afr[4]; uint4 bq[2];
            #pragma unroll
            for (int mi = 0; mi < 4; mi++)
                afr[mi] = *(const uint4*)(wA + mi * 1024 + ks * 256 + lane * 8);
            #pragma unroll
            for (int nb = 0; nb < 2; nb++)
                bq[nb] = *(const uint4*)(wB + nb * 1024 + ks * 256 + lane * 8);
            #pragma unroll
            for (int mi = 0; mi < 4; mi++) {
                mma_f16(acc[mi][0], afr[mi].x, afr[mi].y, afr[mi].z, afr[mi].w, bq[0].x, bq[0].y);
                mma_f16(acc[mi][1], afr[mi].x, afr[mi].y, afr[mi].z, afr[mi].w, bq[0].z, bq[0].w);
                mma_f16(acc[mi][2], afr[mi].x, afr[mi].y, afr[mi].z, afr[mi].w, bq[1].x, bq[1].y);
                mma_f16(acc[mi][3], afr[mi].x, afr[mi].y, afr[mi].z, afr[mi].w, bq[1].z, bq[1].w);
            }
        }
        __syncthreads();
    }

    #pragma unroll
    for (int mi = 0; mi < 4; mi++) {
        #pragma unroll
        for (int ni = 0; ni < 4; ni++) {
            int row = m0 + warp_m * 64 + mi * 16 + g;
            int col = n0 + warp_n * 32 + ni * 8 + tg * 2;
            if (HALF_OUT) {
                __half* C = (__half*)Cv;
                *(__half2*)&C[(size_t)row * ldc + col] =
                    __floats2half2_rn(acc[mi][ni][0], acc[mi][ni][1]);
                *(__half2*)&C[(size_t)(row + 8) * ldc + col] =
                    __floats2half2_rn(acc[mi][ni][2], acc[mi][ni][3]);
            } else {
                float* C = (float*)Cv;
                *(float2*)&C[(size_t)row * ldc + col] =
                    make_float2(acc[mi][ni][0], acc[mi][ni][1]);
                *(float2*)&C[(size_t)(row + 8) * ldc + col] =
                    make_float2(acc[mi][ni][2], acc[mi][ni][3]);
            }
        }
    }
}

// ---------------- prepasses --------------------------------------------------
__global__ void cvt_u_kernel(const float* __restrict__ u) {
    int i = blockIdx.x * 256 + threadIdx.x;
    if (i >= NTOK * DMODEL) return;
    int m = i >> 10, k = i & 1023;
    g_u16[aoffh(m, k, 64)] = __float2half_rn(u[i]);
}
__global__ void pad_win_kernel(const float* __restrict__ W_in) {
    int i = blockIdx.x * 256 + threadIdx.x;
    if (i >= DMODEL * ZXS) return;
    int k = i / ZXS, n = i - k * ZXS;
    float v = (n < DPROJ) ? W_in[(size_t)k * DPROJ + n] : 0.f;
    g_Win[boffh(n, k, 64)] = __float2half_rn(v);
}
__global__ void cvt_wout_kernel(const float* __restrict__ W_out) {
    int i = blockIdx.x * 256 + threadIdx.x;
    if (i >= DINNER * DMODEL) return;
    int k = i >> 10, n = i & 1023;
    g_Wout16[boffh(n, k, 128)] = __float2half_rn(W_out[i]);
}

// ---------------- tiled depthwise causal conv + silu (R13 version) ----------
#define CT_T 64
#define CT_C 128
__global__ void __launch_bounds__(256)
conv_silu_kernel(const float* __restrict__ conv_w, const float* __restrict__ conv_b) {
    __shared__ float sx[CT_T + 3][CT_C];
    int c0 = blockIdx.x * CT_C;
    int t0 = blockIdx.y * CT_T;
    int tid = threadIdx.x;
    bool bstart = ((t0 & (SEQLEN - 1)) == 0);

    for (int i = tid; i < (CT_T + 3) * CT_C; i += 256) {
        int r = i / CT_C, cl = i - r * CT_C;
        int c = c0 + cl;
        float v = 0.f;
        if (c < CONVDIM && !(bstart && r < 3))
            v = __half2float(g_zx[(size_t)(t0 - 3 + r) * ZXS + DINNER + c]);
        sx[r][cl] = v;
    }
    __syncthreads();

    int cl = tid & (CT_C - 1);
    int tbase = (tid >> 7) * (CT_T / 2);
    int c = c0 + cl;
    if (c >= CONVDIM) return;
    float w0 = conv_w[c * 4 + 0], w1 = conv_w[c * 4 + 1];
    float w2 = conv_w[c * 4 + 2], w3 = conv_w[c * 4 + 3];
    float bb = conv_b[c];
    #pragma unroll 8
    for (int i = 0; i < CT_T / 2; i++) {
        int tl = tbase + i;
        float a = bb + sx[tl][cl] * w0 + sx[tl + 1][cl] * w1
                     + sx[tl + 2][cl] * w2 + sx[tl + 3][cl] * w3;
        g_xbc[(size_t)(t0 + tl) * CONVDIM + c] = a / (1.f + __expf(-a));
    }
}

// ---------------- per-chunk: dt, cumsum, M, Y_diag(+D*x), states ------------
#define CHUNK_SMEM ((QC * QC + QC * HEADDIM) * 4)

extern __shared__ float cf_smem[];

__global__ void __launch_bounds__(256)
chunk_kernel(const float* __restrict__ A_log, const float* __restrict__ Dp,
             const float* __restrict__ dt_bias) {
    int h = blockIdx.x, c = blockIdx.y, b = blockIdx.z;
    int t0 = b * SEQLEN + c * QC;
    int tid = threadIdx.x;

    float* sMt = cf_smem;            // sMt[s][q] = M[q][s]
    float* sx  = cf_smem + QC * QC;  // sx[q][p]

    __shared__ float sB[QC][DSTATE];
    __shared__ float sC[QC][DSTATE];
    __shared__ float sE[QC][DSTATE];
    __shared__ float sdt[QC], scs[QC];

    for (int i = tid; i < QC * DSTATE; i += 256) {
        int q = i >> 4, n = i & 15;
        size_t base = (size_t)(t0 + q) * CONVDIM + DINNER;
        sB[q][n] = g_xbc[base + n];
        sC[q][n] = g_xbc[base + DSTATE + n];
    }
    if (tid < QC) {
        float v = __half2float(g_zx[(size_t)(t0 + tid) * ZXS + DINNER + CONVDIM + h]) + dt_bias[h];
        sdt[tid] = (v > 20.f) ? v : log1pf(expf(v));
    }
    #pragma unroll
    for (int j = 0; j < 16; j++) {
        int u = tid + 256 * j;
        int q = u >> 6, p4 = (u & 63) * 4;
        *(float4*)&sx[q * HEADDIM + p4] =
            *(const float4*)&g_xbc[(size_t)(t0 + q) * CONVDIM + h * HEADDIM + p4];
    }
    __syncthreads();

    float A = -expf(A_log[h]);
    if (tid == 0) {
        float run = 0.f;
        for (int q = 0; q < QC; q++) { run += sdt[q] * A; scs[q] = run; }
    }
    __syncthreads();
    if (tid < QC) g_cs[(t0 + tid) * NHEADS + h] = scs[tid];

    float cl = scs[QC - 1];
    for (int i = tid; i < QC * DSTATE; i += 256) {
        int q = i >> 4, n = i & 15;
        sE[q][n] = sB[q][n] * __expf(cl - scs[q]) * sdt[q];
    }
    for (int i = tid; i < QC * QC; i += 256) {
        int q = i >> 6, s = i & 63;
        float v = 0.f;
        if (s <= q) {
            float d = 0.f;
            #pragma unroll
            for (int n = 0; n < DSTATE; n++) d += sC[q][n] * sB[s][n];
            v = __expf(scs[q] - scs[s]) * d * sdt[s];
        }
        sMt[s * QC + q] = v;
    }
    __syncthreads();

    // ---- Y_diag: 8x8 microtile per thread ----
    int q0 = (tid >> 5) * 8;
    int p0 = (tid & 31) * 4;
    int p1 = p0 + 128;

    float acc[8][8];
    #pragma unroll
    for (int i = 0; i < 8; i++)
        #pragma unroll
        for (int j = 0; j < 8; j++) acc[i][j] = 0.f;

    for (int s = 0; s < QC; s++) {
        float4 ma = *(const float4*)&sMt[s * QC + q0];
        float4 mb = *(const float4*)&sMt[s * QC + q0 + 4];
        float4 xa = *(const float4*)&sx[s * HEADDIM + p0];
        float4 xb = *(const float4*)&sx[s * HEADDIM + p1];
        float mv[8] = {ma.x, ma.y, ma.z, ma.w, mb.x, mb.y, mb.z, mb.w};
        float xv[8] = {xa.x, xa.y, xa.z, xa.w, xb.x, xb.y, xb.z, xb.w};
        #pragma unroll
        for (int i = 0; i < 8; i++)
            #pragma unroll
            for (int j = 0; j < 8; j++)
                acc[i][j] += mv[i] * xv[j];
    }

    float Dh = Dp[h];
    #pragma unroll
    for (int i = 0; i < 8; i++) {
        int q = q0 + i;
        size_t yb = (size_t)(t0 + q) * DINNER + h * HEADDIM;
        __half2 h00 = __floats2half2_rn(acc[i][0] + Dh * sx[q * HEADDIM + p0 + 0],
                                        acc[i][1] + Dh * sx[q * HEADDIM + p0 + 1]);
        __half2 h01 = __floats2half2_rn(acc[i][2] + Dh * sx[q * HEADDIM + p0 + 2],
                                        acc[i][3] + Dh * sx[q * HEADDIM + p0 + 3]);
        __half2 h10 = __floats2half2_rn(acc[i][4] + Dh * sx[q * HEADDIM + p1 + 0],
                                        acc[i][5] + Dh * sx[q * HEADDIM + p1 + 1]);
        __half2 h11 = __floats2half2_rn(acc[i][6] + Dh * sx[q * HEADDIM + p1 + 2],
                                        acc[i][7] + Dh * sx[q * HEADDIM + p1 + 3]);
        uint2 pk0, pk1;
        pk0.x = *(unsigned*)&h00; pk0.y = *(unsigned*)&h01;
        pk1.x = *(unsigned*)&h10; pk1.y = *(unsigned*)&h11;
        *(uint2*)&g_y16[yb + p0] = pk0;
        *(uint2*)&g_y16[yb + p1] = pk1;
    }

    // ---- states: thread = one p, 16 n accumulators ----
    float accS[16];
    #pragma unroll
    for (int n = 0; n < 16; n++) accS[n] = 0.f;
    for (int q = 0; q < QC; q++) {
        float xs = sx[q * HEADDIM + tid];
        float4 e0 = *(const float4*)&sE[q][0];
        float4 e1 = *(const float4*)&sE[q][4];
        float4 e2 = *(const float4*)&sE[q][8];
        float4 e3 = *(const float4*)&sE[q][12];
        accS[0]  += e0.x * xs; accS[1]  += e0.y * xs; accS[2]  += e0.z * xs; accS[3]  += e0.w * xs;
        accS[4]  += e1.x * xs; accS[5]  += e1.y * xs; accS[6]  += e1.z * xs; accS[7]  += e1.w * xs;
        accS[8]  += e2.x * xs; accS[9]  += e2.y * xs; accS[10] += e2.z * xs; accS[11] += e2.w * xs;
        accS[12] += e3.x * xs; accS[13] += e3.y * xs; accS[14] += e3.z * xs; accS[15] += e3.w * xs;
    }
    size_t sb = ((size_t)((b * NCHUNK + c) * NHEADS + h)) * HEADDIM * DSTATE
                + (size_t)tid * DSTATE;
    #pragma unroll
    for (int n4 = 0; n4 < 4; n4++)
        *(float4*)&g_states[sb + n4 * 4] =
            make_float4(accS[n4 * 4], accS[n4 * 4 + 1], accS[n4 * 4 + 2], accS[n4 * 4 + 3]);
}

// ---------------- inter-chunk scan ------------------------------------------
__global__ void __launch_bounds__(512) scan_kernel() {
    int pb = blockIdx.x, h = blockIdx.y, b = blockIdx.z;
    int tid = threadIdx.x;
    int pl = tid >> 4, n = tid & 15;
    int p = pb * 32 + pl;
    float carry = 0.f;
    for (int c = 0; c < NCHUNK; c++) {
        size_t idx = ((size_t)((b * NCHUNK + c) * NHEADS + h)) * HEADDIM * DSTATE
                     + (size_t)p * DSTATE + n;
        g_prev[idx] = carry;
        float dec = __expf(g_cs[(b * SEQLEN + c * QC + QC - 1) * NHEADS + h]);
        carry = dec * carry + g_states[idx];
    }
}

// ---------------- Y_off v2: thread = p, prev in registers -------------------
__global__ void __launch_bounds__(256) yoff_kernel() {
    int h = blockIdx.x, c = blockIdx.y, b = blockIdx.z;
    int t0 = b * SEQLEN + c * QC;
    int tid = threadIdx.x;   // = p (0..255)

    __shared__ float sC2[QC][DSTATE];
    __shared__ float sExp[QC];

    // prev[p][0..15] into registers
    size_t pbase = ((size_t)((b * NCHUNK + c) * NHEADS + h)) * HEADDIM * DSTATE
                 + (size_t)tid * DSTATE;
    float4 pr0 = *(const float4*)&g_prev[pbase + 0];
    float4 pr1 = *(const float4*)&g_prev[pbase + 4];
    float4 pr2 = *(const float4*)&g_prev[pbase + 8];
    float4 pr3 = *(const float4*)&g_prev[pbase + 12];

    for (int i = tid; i < QC * DSTATE; i += 256) {
        int q = i >> 4, n = i & 15;
        sC2[q][n] = g_xbc[(size_t)(t0 + q) * CONVDIM + DINNER + DSTATE + n];
    }
    if (tid < QC) sExp[tid] = __expf(g_cs[(t0 + tid) * NHEADS + h]);
    __syncthreads();

    size_t ybase = (size_t)t0 * DINNER + h * HEADDIM + tid;
    #pragma unroll 4
    for (int q = 0; q < QC; q++) {
        float4 c0 = *(const float4*)&sC2[q][0];
        float4 c1 = *(const float4*)&sC2[q][4];
        float4 c2 = *(const float4*)&sC2[q][8];
        float4 c3 = *(const float4*)&sC2[q][12];
        float d = c0.x * pr0.x + c0.y * pr0.y + c0.z * pr0.z + c0.w * pr0.w
                + c1.x * pr1.x + c1.y * pr1.y + c1.z * pr1.z + c1.w * pr1.w
                + c2.x * pr2.x + c2.y * pr2.y + c2.z * pr2.z + c2.w * pr2.w
                + c3.x * pr3.x + c3.y * pr3.y + c3.z * pr3.z + c3.w * pr3.w;
        size_t yi = ybase + (size_t)q * DINNER;
        float yv = __half2float(g_y16[yi]) + sExp[q] * d;
        g_y16[yi] = __float2half_rn(yv);
    }
}

// ---------------- gate + RMSNorm (R13 pattern, fp16 y) ----------------------
__global__ void __launch_bounds__(256) gate_norm_kernel(const float* __restrict__ norm_w) {
    int t = blockIdx.x, tid = threadIdx.x;
    __shared__ float red[256];
    float v[8];
    float ss = 0.f;
    #pragma unroll
    for (int r = 0; r < 8; r++) {
        int i = r * 256 + tid;
        float y = __half2float(g_y16[(size_t)t * DINNER + i]);
        float z = __half2float(g_zx[(size_t)t * ZXS + i]);
        float w = y * (z / (1.f + __expf(-z)));
        v[r] = w;
        ss += w * w;
    }
    red[tid] = ss;
    __syncthreads();
    for (int s = 128; s > 0; s >>= 1) {
        if (tid < s) red[tid] += red[tid + s];
        __syncthreads();
    }
    float scale = rsqrtf(red[0] / (float)DINNER + 1e-5f);
    #pragma unroll
    for (int r = 0; r < 8; r++) {
        int i = r * 256 + tid;
        g_yn[aoffh(t, i, 128)] = __float2half_rn(v[r] * scale * norm_w[i]);
    }
}

// ---------------- launch ----------------------------------------------------
extern "C" void kernel_launch(void* const* d_in, const int* in_sizes, int n_in,
                              void* d_out, int out_size) {
    const float* u       = (const float*)d_in[0];
    const float* W_in    = (const float*)d_in[1];
    const float* conv_w  = (const float*)d_in[2];
    const float* conv_b  = (const float*)d_in[3];
    const float* dt_bias = (const float*)d_in[4];
    const float* A_log   = (const float*)d_in[5];
    const float* Dv      = (const float*)d_in[6];
    const float* norm_w  = (const float*)d_in[7];
    const float* W_out   = (const float*)d_in[8];
    float* out = (float*)d_out;

    void* p;
    cudaGetSymbolAddress(&p, g_zx);     __half* zx   = (__half*)p;
    cudaGetSymbolAddress(&p, g_Win);    __half* win  = (__half*)p;
    cudaGetSymbolAddress(&p, g_u16);    __half* u16  = (__half*)p;
    cudaGetSymbolAddress(&p, g_Wout16); __half* wo16 = (__half*)p;
    cudaGetSymbolAddress(&p, g_yn);     __half* yn   = (__half*)p;

    cudaFuncSetAttribute(mma_gemm<true>,  cudaFuncAttributeMaxDynamicSharedMemorySize, GEMM_SMEM);
    cudaFuncSetAttribute(mma_gemm<false>, cudaFuncAttributeMaxDynamicSharedMemorySize, GEMM_SMEM);
    cudaFuncSetAttribute(chunk_kernel, cudaFuncAttributeMaxDynamicSharedMemorySize, CHUNK_SMEM);

    // prepasses
    pad_win_kernel<<<(DMODEL * ZXS + 255) / 256, 256>>>(W_in);
    cvt_u_kernel<<<(NTOK * DMODEL + 255) / 256, 256>>>(u);
    cvt_wout_kernel<<<(DINNER * DMODEL + 255) / 256, 256>>>(W_out);

    // 1) in-projection (fp16 output)
    mma_gemm<true><<<dim3(ZXS / 128, NTOK / 128), 256, GEMM_SMEM>>>(u16, win, zx, DMODEL, ZXS);

    // 2) conv + silu
    conv_silu_kernel<<<dim3((CONVDIM + CT_C - 1) / CT_C, NTOK / CT_T), 256>>>(conv_w, conv_b);

    // 3) per-chunk
    chunk_kernel<<<dim3(NHEADS, NCHUNK, BATCH), 256, CHUNK_SMEM>>>(A_log, Dv, dt_bias);

    // 4) inter-chunk scan
    scan_kernel<<<dim3(HEADDIM / 32, NHEADS, BATCH), 512>>>();

    // 5) Y_off
    yoff_kernel<<<dim3(NHEADS, NCHUNK, BATCH), 256>>>();

    // 6) gating + RMSNorm
    gate_norm_kernel<<<NTOK, 256>>>(norm_w);

    // 7) out-projection (fp32 output)
    mma_gemm<false><<<dim3(DMODEL / 128, NTOK / 128), 256, GEMM_SMEM>>>(yn, wo16, out, DINNER, DMODEL);
}